// round 17
// baseline (speedup 1.0000x reference)
#include <cuda_runtime.h>
#include <math_constants.h>

// Shapes fixed by setup_inputs: N=8192, K=16
#define NQ     8192
#define KTOP   16
#define GDIM   128                 // grid cells per axis
#define NCELL  (GDIM * GDIM)       // 16384
#define GMINF  (-6.0f)             // grid bounds [-6, 6] (data ~N(0,1))
#define HF     (12.0f / GDIM)      // cell size 0.09375
#define INVHF  (GDIM / 12.0f)
#define RMAXR  8                   // rings before exact brute fallback
#define NRB    16                  // reduce blocks (512 queries each)

// Static scratch (no runtime allocation allowed)
__device__ float4   g_cand[NQ];       // (cx, cy, -0.5|c|^2, 0)
__device__ float4   g_bin[NQ];        // binned: (cx, cy, nh, idx-bits)
__device__ int      g_cellid[NQ];
__device__ unsigned g_hist[NCELL];    // zero-init; scan kernel resets after read
__device__ unsigned g_ofs[NCELL + 1]; // cell start offsets
__device__ unsigned g_cur[NCELL];     // scatter cursors (re-init each run)
__device__ float    g_term[KTOP * NQ];
__device__ float    g_part[NRB];
__device__ unsigned g_done;           // atomicInc wraps -> replay safe

// candidate prep: poly(ch2[i]) and -0.5*|.|^2 (validated FMA chain)
__device__ __forceinline__ float4 poly4(const float2* __restrict__ ch2,
                                        const float* __restrict__ M1,
                                        const float* __restrict__ M2, int i)
{
    float2 a = ch2[i];
    float p  = __fmul_rn(a.x, a.y);
    float y1 = __fmaf_rn(M1[1], a.y, __fmaf_rn(M1[2], a.x, __fmaf_rn(M1[3], p, M1[0])));
    float y2 = __fmaf_rn(M2[1], a.y, __fmaf_rn(M2[2], a.x, __fmaf_rn(M2[3], p, M2[0])));
    float nh = -0.5f * __fmaf_rn(y1, y1, __fmul_rn(y2, y2));
    return make_float4(y1, y2, nh, 0.0f);
}

// order-preserving float->uint key (monotone)
__device__ __forceinline__ unsigned fkey(float f)
{
    unsigned u = __float_as_uint(f);
    return u ^ ((unsigned)((int)u >> 31) | 0x80000000u);
}

// stable sorted-insert by total order (s desc, idx asc). Order-independent
// result -> deterministic output despite nondeterministic bin order.
__device__ __forceinline__ void ins16(float (&l)[KTOP], int (&li)[KTOP],
                                      float s, int ci)
{
    bool en = (s > l[KTOP - 1]) || (s == l[KTOP - 1] && ci < li[KTOP - 1]);
    if (en) {
#pragma unroll
        for (int m = KTOP - 1; m >= 1; --m) {
            bool up   = (s > l[m - 1]) || (s == l[m - 1] && ci < li[m - 1]);
            bool here = !up && ((s > l[m]) || (s == l[m] && ci < li[m]));
            float nd  = up ? l[m - 1]  : (here ? s  : l[m]);
            int   ni  = up ? li[m - 1] : (here ? ci : li[m]);
            l[m] = nd; li[m] = ni;
        }
        bool top = (s > l[0]) || (s == l[0] && ci < li[0]);
        if (top) { l[0] = s; li[0] = ci; }
    }
}

// ---------------------------------------------------------------------------
// Kernel A: prep + bin histogram.
// ---------------------------------------------------------------------------
__global__ __launch_bounds__(128)
void prep_kernel(const float2* __restrict__ ch2,
                 const float* __restrict__ M1, const float* __restrict__ M2)
{
    int i = blockIdx.x * 128 + threadIdx.x;
    float4 c = poly4(ch2, M1, M2, i);
    g_cand[i] = c;
    int cx = min(max((int)((c.x - GMINF) * INVHF), 0), GDIM - 1);
    int cy = min(max((int)((c.y - GMINF) * INVHF), 0), GDIM - 1);
    int cell = cy * GDIM + cx;
    g_cellid[i] = cell;
    atomicAdd(&g_hist[cell], 1u);
}

// ---------------------------------------------------------------------------
// Kernel B: exclusive scan of 16384 bins (1 block), init cursors,
// reset histogram for the next graph replay.
// ---------------------------------------------------------------------------
__global__ __launch_bounds__(1024)
void scan_kernel()
{
    __shared__ unsigned sm[1024];
    const int t = threadIdx.x;
    unsigned v[16], run = 0;
#pragma unroll
    for (int i = 0; i < 16; ++i) { v[i] = g_hist[t * 16 + i]; run += v[i]; }
    sm[t] = run;
    __syncthreads();
    for (int off = 1; off < 1024; off <<= 1) {
        unsigned add = (t >= off) ? sm[t - off] : 0u;
        __syncthreads();
        sm[t] += add;
        __syncthreads();
    }
    unsigned acc = sm[t] - run;   // exclusive base
#pragma unroll
    for (int i = 0; i < 16; ++i) {
        g_ofs[t * 16 + i] = acc;
        g_cur[t * 16 + i] = acc;
        acc += v[i];
        g_hist[t * 16 + i] = 0u;  // reset for next replay
    }
    if (t == 1023) g_ofs[NCELL] = acc;
}

// ---------------------------------------------------------------------------
// Kernel C: scatter candidates into bins (order within bin arbitrary;
// select comparator is order-independent).
// ---------------------------------------------------------------------------
__global__ __launch_bounds__(128)
void scatter_kernel()
{
    int i = blockIdx.x * 128 + threadIdx.x;
    int cell = g_cellid[i];
    unsigned pos = atomicAdd(&g_cur[cell], 1u);
    float4 c = g_cand[i];
    g_bin[pos] = make_float4(c.x, c.y, c.z, __int_as_float(i));
}

// span of candidates for contiguous cells [c0, c1): lanes stride, coalesced
__device__ __forceinline__ void scan_span(int c0, int c1, float2 q, int lane,
                                          float (&l)[KTOP], int (&li)[KTOP])
{
    unsigned b0 = __ldg(&g_ofs[c0]);
    unsigned b1 = __ldg(&g_ofs[c1]);
    for (unsigned i = b0 + lane; i < b1; i += 32) {
        float4 b = __ldg(&g_bin[i]);
        float s = __fmaf_rn(q.y, b.y, __fmaf_rn(q.x, b.x, b.z));
        ins16(l, li, s, __float_as_int(b.w));
    }
}

// ---------------------------------------------------------------------------
// Kernel D: warp-per-query exact ring-search KNN + scrambled exp emission.
// Termination: after ring R, all unscanned candidates (incl. any clamped
// outside the grid) lie outside square S_R, so their dist >= db =
// point-to-S_R-boundary margin. Stop when >=16 evaluated candidates have
// dist <= 0.995*db^2 (strict margin -> no FP boundary ambiguity). Rare
// non-terminating queries do an exact brute scan. Final 16-round
// redux-max(key)+redux-min(idx) == (s desc, idx asc) == lax.top_k order.
// ---------------------------------------------------------------------------
__global__ __launch_bounds__(128)
void knn_kernel(const float2* __restrict__ ch1)
{
    const float scale = -0.5f / 2.25f;   // -0.5 / sigma2^2, sigma2 = 1.5
    const int j    = (blockIdx.x * 128 + threadIdx.x) >> 5;
    const int lane = threadIdx.x & 31;

    const float2 q = ch1[j];
    const float xx = __fmaf_rn(q.x, q.x, __fmul_rn(q.y, q.y));

    float l[KTOP];
    int   li[KTOP];
#pragma unroll
    for (int m = 0; m < KTOP; ++m) { l[m] = -CUDART_INF_F; li[m] = 0x7fffffff; }

    const int icx = min(max((int)((q.x - GMINF) * INVHF), 0), GDIM - 1);
    const int icy = min(max((int)((q.y - GMINF) * INVHF), 0), GDIM - 1);

    bool found = false;
    for (int R = 0; R <= RMAXR && !found; ++R) {
        int y0 = max(icy - R, 0), y1 = min(icy + R, GDIM - 1);
        for (int y = y0; y <= y1; ++y) {
            if (y == icy - R || y == icy + R) {       // full row span
                int xs = max(icx - R, 0), xe = min(icx + R, GDIM - 1);
                scan_span(y * GDIM + xs, y * GDIM + xe + 1, q, lane, l, li);
            } else {                                   // two side cells
                if (icx - R >= 0)
                    scan_span(y * GDIM + icx - R, y * GDIM + icx - R + 1,
                              q, lane, l, li);
                if (icx + R <= GDIM - 1)
                    scan_span(y * GDIM + icx + R, y * GDIM + icx + R + 1,
                              q, lane, l, li);
            }
        }
        if (R >= 1) {
            float Lx = GMINF + (icx - R) * HF, Rx = GMINF + (icx + R + 1) * HF;
            float Ly = GMINF + (icy - R) * HF, Ry = GMINF + (icy + R + 1) * HF;
            float db = fminf(fminf(q.x - Lx, Rx - q.x),
                             fminf(q.y - Ly, Ry - q.y));
            if (db > 0.0f) {
                float sth = 0.5f * (xx - 0.995f * db * db);
                int cnt = 0;
#pragma unroll
                for (int m = 0; m < KTOP; ++m) cnt += (l[m] >= sth) ? 1 : 0;
                cnt = __reduce_add_sync(0xffffffffu, cnt);
                if (cnt >= KTOP) found = true;
            }
        }
    }

    if (!found) {   // exact brute fallback (rare tail queries)
#pragma unroll
        for (int m = 0; m < KTOP; ++m) { l[m] = -CUDART_INF_F; li[m] = 0x7fffffff; }
        for (int i = lane; i < NQ; i += 32) {
            float4 b = __ldg(&g_bin[i]);
            float s = __fmaf_rn(q.y, b.y, __fmaf_rn(q.x, b.x, b.z));
            ins16(l, li, s, __float_as_int(b.w));
        }
    }

    // 16-round warp select (validated) + scramble-inverted emission
    int myidx = 0;
#pragma unroll
    for (int k = 0; k < KTOP; ++k) {
        unsigned key = fkey(l[0]);
        unsigned mx  = __reduce_max_sync(0xffffffffu, key);
        unsigned cnd = (key == mx) ? (unsigned)li[0] : 0xffffffffu;
        unsigned win = __reduce_min_sync(0xffffffffu, cnd);
        if (lane == k) myidx = (int)win;
        bool pop = (key == mx) && ((unsigned)li[0] == win);
#pragma unroll
        for (int m = 0; m < KTOP - 1; ++m) {
            l[m]  = pop ? l[m + 1]  : l[m];
            li[m] = pop ? li[m + 1] : li[m];
        }
        if (pop) { l[KTOP - 1] = -CUDART_INF_F; li[KTOP - 1] = 0x7fffffff; }
    }

    if (lane < KTOP) {
        const int n = ((j & 511) << 4) + lane;   // target query
        const int k = j >> 9;                    // target k-slot
        float4 c = g_cand[myidx];
        float2 x = ch1[n];
        float dy1 = x.x - c.x;
        float dy2 = x.y - c.y;
        g_term[k * NQ + n] =
            __expf(scale * __fmaf_rn(dy2, dy2, __fmul_rn(dy1, dy1)));
    }
}

// ---------------------------------------------------------------------------
// Kernel E (validated R12/R16): term-sum + log + partials + fused final.
// ---------------------------------------------------------------------------
__global__ __launch_bounds__(512)
void reduce_kernel(float* __restrict__ out)
{
    const int tid = threadIdx.x;
    const int n   = blockIdx.x * 512 + tid;

    float esum = 0.0f;
#pragma unroll
    for (int k = 0; k < KTOP; ++k)
        esum += g_term[k * NQ + n];

    float expD = esum * (1.0f / (float)NQ);
    float v = (expD != 0.0f) ? __logf(expD) : 0.0f;

    __shared__ float red[512];
    __shared__ bool  last;
    red[tid] = v;
    __syncthreads();
#pragma unroll
    for (int off = 256; off > 0; off >>= 1) {
        if (tid < off) red[tid] += red[tid + off];
        __syncthreads();
    }
    if (tid == 0) {
        g_part[blockIdx.x] = red[0];
        __threadfence();
        unsigned old = atomicInc(&g_done, NRB - 1);   // wraps to 0 on last
        last = (old == NRB - 1);
    }
    __syncthreads();

    if (last && tid < 32) {
        float s = (tid < NRB) ? g_part[tid] : 0.0f;
#pragma unroll
        for (int o = 16; o > 0; o >>= 1)
            s += __shfl_xor_sync(0xffffffffu, s, o);
        if (tid == 0) out[0] = -s;
    }
}

// ---------------------------------------------------------------------------
extern "C" void kernel_launch(void* const* d_in, const int* in_sizes, int n_in,
                              void* d_out, int out_size)
{
    const float2* ch1 = (const float2*)d_in[0];
    const float2* ch2 = (const float2*)d_in[1];
    const float*  M1  = (const float*)d_in[2];
    const float*  M2  = (const float*)d_in[3];
    float* out = (float*)d_out;

    prep_kernel<<<NQ / 128, 128>>>(ch2, M1, M2);      // bin histogram
    scan_kernel<<<1, 1024>>>();                       // offsets + cursors
    scatter_kernel<<<NQ / 128, 128>>>();              // fill bins
    knn_kernel<<<NQ * 32 / 128, 128>>>(ch1);          // ring KNN + emission
    reduce_kernel<<<NRB, 512>>>(out);                 // sum + log + final
}